// round 10
// baseline (speedup 1.0000x reference)
#include <cuda_runtime.h>
#include <cstdint>

#define N_NODES 100000
#define N_EDGES 1600000
#define D_IN    256
#define N_HEADS 4
#define D_OUT   32
#define D_HID   128
#define NEG_SLOPE 0.2f

#define SCAN_B 512
#define NB ((N_NODES + SCAN_B - 1) / SCAN_B)   // 196

#define ROWS_PER_BLK 512
#define GEMM_BLKS ((N_NODES + ROWS_PER_BLK - 1) / ROWS_PER_BLK)  // 196

// ---------------- scratch (static device globals) ----------------------------
__device__ float  g_ft[N_NODES * D_HID];
__device__ float  g_el[N_NODES * N_HEADS];
__device__ float  g_er[N_NODES * N_HEADS];
__device__ int    g_cnt[N_NODES];
__device__ int    g_scan[N_NODES];
__device__ int    g_off[N_NODES];
__device__ int    g_cursor[N_NODES];
__device__ int    g_btot[256];
__device__ int    g_boff[256];
__device__ int    g_srcv[N_EDGES];

// ---------------- K: histogram of dst ------------------------------------------
__global__ void k_hist(const int* __restrict__ dst) {
    int e = blockIdx.x * blockDim.x + threadIdx.x;
    if (e >= N_EDGES) return;
    int d = dst[e];
    if ((unsigned)d < N_NODES) atomicAdd(&g_cnt[d], 1);
}

// ---------------- K: scan stages ---------------------------------------------------
__global__ __launch_bounds__(SCAN_B) void k_scan1() {
    __shared__ int sh[SCAN_B];
    int i = blockIdx.x * SCAN_B + threadIdx.x;
    int v = (i < N_NODES) ? g_cnt[i] : 0;
    sh[threadIdx.x] = v;
    __syncthreads();
#pragma unroll
    for (int off = 1; off < SCAN_B; off <<= 1) {
        int t = (threadIdx.x >= off) ? sh[threadIdx.x - off] : 0;
        __syncthreads();
        sh[threadIdx.x] += t;
        __syncthreads();
    }
    if (i < N_NODES) g_scan[i] = sh[threadIdx.x];
    if (threadIdx.x == SCAN_B - 1) g_btot[blockIdx.x] = sh[SCAN_B - 1];
}

__global__ __launch_bounds__(256) void k_scan2() {
    __shared__ int sh[256];
    int tid = threadIdx.x;
    int v = (tid < NB) ? g_btot[tid] : 0;
    sh[tid] = v;
    __syncthreads();
#pragma unroll
    for (int off = 1; off < 256; off <<= 1) {
        int t = (tid >= off) ? sh[tid - off] : 0;
        __syncthreads();
        sh[tid] += t;
        __syncthreads();
    }
    if (tid < NB) g_boff[tid] = sh[tid] - v;
}

__global__ __launch_bounds__(SCAN_B) void k_scan3() {
    int i = blockIdx.x * SCAN_B + threadIdx.x;
    if (i < N_NODES) {
        int off = g_scan[i] - g_cnt[i] + g_boff[blockIdx.x];
        g_off[i]    = off;
        g_cursor[i] = off;
    }
}

// ---------------- K: scatter (src-only) ----------------------------------------------
__global__ void k_scatter(const int* __restrict__ src, const int* __restrict__ dst) {
    int e = blockIdx.x * blockDim.x + threadIdx.x;
    if (e >= N_EDGES) return;
    int s = src[e], d = dst[e];
    if ((unsigned)s >= N_NODES || (unsigned)d >= N_NODES) return;
    int pos = atomicAdd(&g_cursor[d], 1);
    g_srcv[pos] = s;
}

// ---------------- helpers -------------------------------------------------------------
__device__ __forceinline__ float trunc_tf32(float f) {
    return __uint_as_float(__float_as_uint(f) & 0xFFFFE000u);
}
__device__ __forceinline__ uint32_t smem_u32(const void* p) {
    uint32_t a;
    asm("{ .reg .u64 t; cvta.to.shared.u64 t, %1; cvt.u32.u64 %0, t; }" : "=r"(a) : "l"(p));
    return a;
}
__device__ __forceinline__ void cp16(void* sdst, const void* gsrc, int srcbytes) {
    asm volatile("cp.async.cg.shared.global [%0], [%1], 16, %2;"
                 :: "r"(smem_u32(sdst)), "l"(gsrc), "r"(srcbytes));
}
#define CP_COMMIT() asm volatile("cp.async.commit_group;" ::: "memory")
#define CP_WAIT(n)  asm volatile("cp.async.wait_group %0;" :: "n"(n) : "memory")

__device__ __forceinline__ void mma_tf32_m16n8k8(float* d, const float* a, float b0, float b1) {
    asm volatile(
        "mma.sync.aligned.m16n8k8.row.col.f32.tf32.tf32.f32 "
        "{%0,%1,%2,%3}, {%4,%5,%6,%7}, {%8,%9}, {%0,%1,%2,%3};"
        : "+f"(d[0]), "+f"(d[1]), "+f"(d[2]), "+f"(d[3])
        : "r"(__float_as_uint(a[0])), "r"(__float_as_uint(a[1])),
          "r"(__float_as_uint(a[2])), "r"(__float_as_uint(a[3])),
          "r"(__float_as_uint(b0)),  "r"(__float_as_uint(b1)));
}

// SMEM layout (floats): W chunks [0..7] (each 128 rows x 36), A double buffer, al/ar
#define LDPAD 36
#define TILE_FLOATS (128 * LDPAD)              // 4608 floats
#define OFF_W(c)  ((c) * TILE_FLOATS)          // 8 chunks: full W resident
#define OFF_A(b)  ((8 + (b)) * TILE_FLOATS)    // 2 A buffers
#define OFF_ALS   (10 * TILE_FLOATS)
#define OFF_ARS   (10 * TILE_FLOATS + 128)
#define SMEM_FLOATS (10 * TILE_FLOATS + 256)
#define SMEM_BYTES (SMEM_FLOATS * 4)           // 185,344 bytes

// ---------------- K: cp.async GEMM, W resident, 4 m-tiles per block, fused el/er -------
__global__ __launch_bounds__(256) void k_gemm_mma(const float* __restrict__ x,
                                                  const float* __restrict__ w,
                                                  const float* __restrict__ al,
                                                  const float* __restrict__ ar) {
    extern __shared__ __align__(16) float smem[];
    float* al_s = smem + OFF_ALS;
    float* ar_s = smem + OFF_ARS;

    const int tid  = threadIdx.x;
    const int lane = tid & 31;
    const int warp = tid >> 5;
    const int wm   = warp >> 1;          // 0..3
    const int wn   = warp & 1;           // 0..1
    const int ty   = lane >> 2;          // 0..7
    const int tx   = lane & 3;           // 0..3
    const int blkRow = blockIdx.x * ROWS_PER_BLK;

    if (tid < 128) { al_s[tid] = al[tid]; ar_s[tid] = ar[tid]; }

    // ---- load ALL of W once (8 chunks of 128 rows x 32 k), one commit group ----
#pragma unroll
    for (int c = 0; c < 8; c++) {
#pragma unroll
        for (int t = 0; t < 4; t++) {
            int j   = t * 256 + tid;
            int row = j >> 3;
            int kq  = (j & 7) << 2;
            cp16(smem + OFF_W(c) + row * LDPAD + kq,
                 w + (size_t)row * D_IN + c * 32 + kq, 16);
        }
    }
    CP_COMMIT();

    // A prefetch: global chunk g in 0..31 (tile = g>>3, kchunk = g&7, buf = g&1)
    auto prefA = [&](int g) {
        int tt = g >> 3, cc = g & 7, b = g & 1;
        int rb = blkRow + tt * 128;
#pragma unroll
        for (int t = 0; t < 4; t++) {
            int j   = t * 256 + tid;
            int row = j >> 3;
            int kq  = (j & 7) << 2;
            int grow = rb + row;
            cp16(smem + OFF_A(b) + row * LDPAD + kq,
                 x + (size_t)grow * D_IN + cc * 32 + kq,
                 grow < N_NODES ? 16 : 0);
        }
        CP_COMMIT();
    };

    float acc[2][8][4];
#pragma unroll
    for (int mt = 0; mt < 2; mt++)
#pragma unroll
        for (int nt = 0; nt < 8; nt++)
#pragma unroll
            for (int i = 0; i < 4; i++) acc[mt][nt][i] = 0.0f;

    prefA(0);

    for (int g = 0; g < 32; g++) {
        int buf = g & 1;
        if (g + 1 < 32) { prefA(g + 1); CP_WAIT(1); }
        else            { CP_WAIT(0); }
        __syncthreads();

        const float* A = smem + OFF_A(buf);
        const float* B = smem + OFF_W(g & 7);
#pragma unroll
        for (int ks = 0; ks < 4; ks++) {
            int koff = ks * 8;
            float ah[2][4], alo[2][4];
#pragma unroll
            for (int mt = 0; mt < 2; mt++) {
                int r = wm * 32 + mt * 16 + ty;
                float a0 = A[(r    ) * LDPAD + koff + tx];
                float a1 = A[(r + 8) * LDPAD + koff + tx];
                float a2 = A[(r    ) * LDPAD + koff + tx + 4];
                float a3 = A[(r + 8) * LDPAD + koff + tx + 4];
                ah[mt][0] = trunc_tf32(a0); alo[mt][0] = a0 - ah[mt][0];
                ah[mt][1] = trunc_tf32(a1); alo[mt][1] = a1 - ah[mt][1];
                ah[mt][2] = trunc_tf32(a2); alo[mt][2] = a2 - ah[mt][2];
                ah[mt][3] = trunc_tf32(a3); alo[mt][3] = a3 - ah[mt][3];
            }
#pragma unroll
            for (int nt = 0; nt < 8; nt++) {
                int n = wn * 64 + nt * 8 + ty;
                float b0 = B[n * LDPAD + koff + tx];
                float b1 = B[n * LDPAD + koff + tx + 4];
                float bh0 = trunc_tf32(b0), bl0 = b0 - bh0;
                float bh1 = trunc_tf32(b1), bl1 = b1 - bh1;
#pragma unroll
                for (int mt = 0; mt < 2; mt++) {
                    mma_tf32_m16n8k8(acc[mt][nt], ah[mt],  bh0, bh1);
                    mma_tf32_m16n8k8(acc[mt][nt], ah[mt],  bl0, bl1);
                    mma_tf32_m16n8k8(acc[mt][nt], alo[mt], bh0, bh1);
                }
            }
        }
        __syncthreads();    // all reads of A-buf done before refill at g+2

        // ---- per-tile epilogue after the 8th k-chunk ----
        if ((g & 7) == 7) {
            int rowBase = blkRow + (g >> 3) * 128;
#pragma unroll
            for (int mt = 0; mt < 2; mt++) {
#pragma unroll
                for (int half = 0; half < 2; half++) {
                    int row = rowBase + wm * 32 + mt * 16 + ty + half * 8;
                    bool valid = row < N_NODES;
                    float el0 = 0.f, el1 = 0.f, er0 = 0.f, er1 = 0.f;
#pragma unroll
                    for (int nt = 0; nt < 8; nt++) {
                        int col = wn * 64 + nt * 8 + tx * 2;
                        float d0 = acc[mt][nt][half * 2 + 0];
                        float d1 = acc[mt][nt][half * 2 + 1];
                        if (valid)
                            *(float2*)(g_ft + (size_t)row * D_HID + col) = make_float2(d0, d1);
                        float l0 = al_s[col], l1 = al_s[col + 1];
                        float r0 = ar_s[col], r1 = ar_s[col + 1];
                        if (nt < 4) { el0 += d0 * l0 + d1 * l1; er0 += d0 * r0 + d1 * r1; }
                        else        { el1 += d0 * l0 + d1 * l1; er1 += d0 * r0 + d1 * r1; }
                    }
#pragma unroll
                    for (int off = 1; off <= 2; off <<= 1) {
                        el0 += __shfl_xor_sync(0xffffffffu, el0, off);
                        el1 += __shfl_xor_sync(0xffffffffu, el1, off);
                        er0 += __shfl_xor_sync(0xffffffffu, er0, off);
                        er1 += __shfl_xor_sync(0xffffffffu, er1, off);
                    }
                    if (tx == 0 && valid) {
                        int h0 = 2 * wn;
                        g_el[row * N_HEADS + h0]     = el0;
                        g_el[row * N_HEADS + h0 + 1] = el1;
                        g_er[row * N_HEADS + h0]     = er0;
                        g_er[row * N_HEADS + h0 + 1] = er1;
                    }
                }
            }
            // reset accumulators for next tile
#pragma unroll
            for (int mt = 0; mt < 2; mt++)
#pragma unroll
                for (int nt = 0; nt < 8; nt++)
#pragma unroll
                    for (int i = 0; i < 4; i++) acc[mt][nt][i] = 0.0f;
        }
    }
}

__device__ __forceinline__ float lrelu(float v) { return v > 0.0f ? v : NEG_SLOPE * v; }

// ---------------- K: aggregation (warp/node, lane-per-4-features, inline exp) ----------
__global__ __launch_bounds__(256) void k_agg2(float* __restrict__ out) {
    int gw   = (blockIdx.x * blockDim.x + threadIdx.x) >> 5;
    int lane = threadIdx.x & 31;
    if (gw >= N_NODES) return;
    int cnt   = g_cnt[gw];
    int start = g_off[gw];
    int hsel  = lane >> 3;

    float er_u = g_er[gw * N_HEADS + hsel];

    float4 acc = make_float4(0.f, 0.f, 0.f, 0.f);
    float  dn  = 0.f;

    const int* srcA = g_srcv + start;

    int i = 0;
    for (; i + 4 <= cnt; i += 4) {
        int s0 = srcA[i], s1 = srcA[i + 1], s2 = srcA[i + 2], s3 = srcA[i + 3];
        float ex0 = expf(lrelu(g_el[s0 * N_HEADS + hsel] + er_u));
        float ex1 = expf(lrelu(g_el[s1 * N_HEADS + hsel] + er_u));
        float ex2 = expf(lrelu(g_el[s2 * N_HEADS + hsel] + er_u));
        float ex3 = expf(lrelu(g_el[s3 * N_HEADS + hsel] + er_u));
        float4 f0 = *(const float4*)(g_ft + (size_t)s0 * D_HID + lane * 4);
        float4 f1 = *(const float4*)(g_ft + (size_t)s1 * D_HID + lane * 4);
        float4 f2 = *(const float4*)(g_ft + (size_t)s2 * D_HID + lane * 4);
        float4 f3 = *(const float4*)(g_ft + (size_t)s3 * D_HID + lane * 4);
        acc.x += ex0 * f0.x + ex1 * f1.x + ex2 * f2.x + ex3 * f3.x;
        acc.y += ex0 * f0.y + ex1 * f1.y + ex2 * f2.y + ex3 * f3.y;
        acc.z += ex0 * f0.z + ex1 * f1.z + ex2 * f2.z + ex3 * f3.z;
        acc.w += ex0 * f0.w + ex1 * f1.w + ex2 * f2.w + ex3 * f3.w;
        dn    += ex0 + ex1 + ex2 + ex3;
    }
    for (; i < cnt; i++) {
        int s = srcA[i];
        float ex = expf(lrelu(g_el[s * N_HEADS + hsel] + er_u));
        float4 f = *(const float4*)(g_ft + (size_t)s * D_HID + lane * 4);
        acc.x += ex * f.x; acc.y += ex * f.y;
        acc.z += ex * f.z; acc.w += ex * f.w;
        dn += ex;
    }

    float4 o;
    if (cnt) {
        o.x = acc.x / dn; o.y = acc.y / dn;
        o.z = acc.z / dn; o.w = acc.w / dn;
    } else {
        o = make_float4(0.f, 0.f, 0.f, 0.f);
    }
    *(float4*)(out + (size_t)gw * D_HID + lane * 4) = o;
}

// ---------------- launch -----------------------------------------------------------------
extern "C" void kernel_launch(void* const* d_in, const int* in_sizes, int n_in,
                              void* d_out, int out_size) {
    const float* x   = (const float*)d_in[0];
    const float* w   = (const float*)d_in[1];
    const float* al  = (const float*)d_in[2];
    const float* ar  = (const float*)d_in[3];
    const int*   src = (const int*)d_in[4];
    const int*   dst = (const int*)d_in[5];
    float*       out = (float*)d_out;

    static bool init_done = false;
    static cudaStream_t s2;
    static cudaEvent_t evFork, evJoin;
    static void* cntAddr = nullptr;
    if (!init_done) {
        cudaFuncSetAttribute(k_gemm_mma, cudaFuncAttributeMaxDynamicSharedMemorySize, SMEM_BYTES);
        cudaStreamCreateWithFlags(&s2, cudaStreamNonBlocking);
        cudaEventCreateWithFlags(&evFork, cudaEventDisableTiming);
        cudaEventCreateWithFlags(&evJoin, cudaEventDisableTiming);
        cudaGetSymbolAddress(&cntAddr, g_cnt);
        init_done = true;
    }

    // fork: edge-indexing chain on s2, independent of the GEMM
    cudaEventRecord(evFork, 0);
    cudaStreamWaitEvent(s2, evFork, 0);
    cudaMemsetAsync(cntAddr, 0, N_NODES * sizeof(int), s2);
    k_hist<<<(N_EDGES + 255) / 256, 256, 0, s2>>>(dst);
    k_scan1<<<NB, SCAN_B, 0, s2>>>();
    k_scan2<<<1, 256, 0, s2>>>();
    k_scan3<<<NB, SCAN_B, 0, s2>>>();
    k_scatter<<<(N_EDGES + 255) / 256, 256, 0, s2>>>(src, dst);
    cudaEventRecord(evJoin, s2);

    k_gemm_mma<<<GEMM_BLKS, 256, SMEM_BYTES>>>(x, w, al, ar);

    // join: agg2 needs srcv/cnt/off (s2) + ft/el/er (GEMM)
    cudaStreamWaitEvent(0, evJoin, 0);
    k_agg2<<<(N_NODES * 32 + 255) / 256, 256>>>(out);
}

// round 11
// speedup vs baseline: 1.2162x; 1.2162x over previous
#include <cuda_runtime.h>
#include <cuda_fp16.h>
#include <cstdint>

#define N_NODES 100000
#define N_EDGES 1600000
#define D_IN    256
#define N_HEADS 4
#define D_OUT   32
#define D_HID   128
#define NEG_SLOPE 0.2f

#define SCAN_B 512
#define NB ((N_NODES + SCAN_B - 1) / SCAN_B)   // 196

// ---------------- scratch (static device globals) ----------------------------
__device__ uint32_t g_fth[N_NODES * 64];     // ft as half2 pairs: 25.6 MB
__device__ float  g_el[N_NODES * N_HEADS];
__device__ float  g_er[N_NODES * N_HEADS];
__device__ int    g_cnt[N_NODES];
__device__ int    g_scan[N_NODES];
__device__ int    g_off[N_NODES];
__device__ int    g_cursor[N_NODES];
__device__ int    g_btot[256];
__device__ int    g_boff[256];
__device__ int    g_srcv[N_EDGES];

// ---------------- K: histogram of dst ------------------------------------------
__global__ void k_hist(const int* __restrict__ dst) {
    int e = blockIdx.x * blockDim.x + threadIdx.x;
    if (e >= N_EDGES) return;
    int d = dst[e];
    if ((unsigned)d < N_NODES) atomicAdd(&g_cnt[d], 1);
}

// ---------------- K: scan stages ---------------------------------------------------
__global__ __launch_bounds__(SCAN_B) void k_scan1() {
    __shared__ int sh[SCAN_B];
    int i = blockIdx.x * SCAN_B + threadIdx.x;
    int v = (i < N_NODES) ? g_cnt[i] : 0;
    sh[threadIdx.x] = v;
    __syncthreads();
#pragma unroll
    for (int off = 1; off < SCAN_B; off <<= 1) {
        int t = (threadIdx.x >= off) ? sh[threadIdx.x - off] : 0;
        __syncthreads();
        sh[threadIdx.x] += t;
        __syncthreads();
    }
    if (i < N_NODES) g_scan[i] = sh[threadIdx.x];
    if (threadIdx.x == SCAN_B - 1) g_btot[blockIdx.x] = sh[SCAN_B - 1];
}

__global__ __launch_bounds__(256) void k_scan2() {
    __shared__ int sh[256];
    int tid = threadIdx.x;
    int v = (tid < NB) ? g_btot[tid] : 0;
    sh[tid] = v;
    __syncthreads();
#pragma unroll
    for (int off = 1; off < 256; off <<= 1) {
        int t = (tid >= off) ? sh[tid - off] : 0;
        __syncthreads();
        sh[tid] += t;
        __syncthreads();
    }
    if (tid < NB) g_boff[tid] = sh[tid] - v;
}

__global__ __launch_bounds__(SCAN_B) void k_scan3() {
    int i = blockIdx.x * SCAN_B + threadIdx.x;
    if (i < N_NODES) {
        int off = g_scan[i] - g_cnt[i] + g_boff[blockIdx.x];
        g_off[i]    = off;
        g_cursor[i] = off;
    }
}

// ---------------- K: scatter (src-only) ----------------------------------------------
__global__ void k_scatter(const int* __restrict__ src, const int* __restrict__ dst) {
    int e = blockIdx.x * blockDim.x + threadIdx.x;
    if (e >= N_EDGES) return;
    int s = src[e], d = dst[e];
    if ((unsigned)s >= N_NODES || (unsigned)d >= N_NODES) return;
    int pos = atomicAdd(&g_cursor[d], 1);
    g_srcv[pos] = s;
}

// ---------------- helpers -------------------------------------------------------------
__device__ __forceinline__ float trunc_tf32(float f) {
    return __uint_as_float(__float_as_uint(f) & 0xFFFFE000u);
}
__device__ __forceinline__ uint32_t smem_u32(const void* p) {
    uint32_t a;
    asm("{ .reg .u64 t; cvta.to.shared.u64 t, %1; cvt.u32.u64 %0, t; }" : "=r"(a) : "l"(p));
    return a;
}
__device__ __forceinline__ void cp16(void* sdst, const void* gsrc, int srcbytes) {
    asm volatile("cp.async.cg.shared.global [%0], [%1], 16, %2;"
                 :: "r"(smem_u32(sdst)), "l"(gsrc), "r"(srcbytes));
}
#define CP_COMMIT() asm volatile("cp.async.commit_group;" ::: "memory")
#define CP_WAIT(n)  asm volatile("cp.async.wait_group %0;" :: "n"(n) : "memory")

__device__ __forceinline__ void mma_tf32_m16n8k8(float* d, const float* a, float b0, float b1) {
    asm volatile(
        "mma.sync.aligned.m16n8k8.row.col.f32.tf32.tf32.f32 "
        "{%0,%1,%2,%3}, {%4,%5,%6,%7}, {%8,%9}, {%0,%1,%2,%3};"
        : "+f"(d[0]), "+f"(d[1]), "+f"(d[2]), "+f"(d[3])
        : "r"(__float_as_uint(a[0])), "r"(__float_as_uint(a[1])),
          "r"(__float_as_uint(a[2])), "r"(__float_as_uint(a[3])),
          "r"(__float_as_uint(b0)),  "r"(__float_as_uint(b1)));
}

// SMEM layout: A double buffer + B double buffer + al/ar (same as the 223.6us config)
#define LDPAD 36
#define TILE_FLOATS (128 * LDPAD)
#define OFF_A(b) ((b) * TILE_FLOATS)
#define OFF_B(b) ((2 + (b)) * TILE_FLOATS)
#define OFF_ALS  (4 * TILE_FLOATS)
#define OFF_ARS  (4 * TILE_FLOATS + 128)
#define SMEM_FLOATS (4 * TILE_FLOATS + 256)
#define SMEM_BYTES (SMEM_FLOATS * 4)

// ---------------- K: cp.async double-buffered 3xTF32 GEMM + fused el/er -----------
__global__ __launch_bounds__(256) void k_gemm_mma(const float* __restrict__ x,
                                                  const float* __restrict__ w,
                                                  const float* __restrict__ al,
                                                  const float* __restrict__ ar) {
    extern __shared__ __align__(16) float smem[];
    float* al_s = smem + OFF_ALS;
    float* ar_s = smem + OFF_ARS;

    const int tid  = threadIdx.x;
    const int lane = tid & 31;
    const int warp = tid >> 5;
    const int wm   = warp >> 1;
    const int wn   = warp & 1;
    const int ty   = lane >> 2;
    const int tx   = lane & 3;
    const int rowBase = blockIdx.x * 128;

    if (tid < 128) { al_s[tid] = al[tid]; ar_s[tid] = ar[tid]; }

    float acc[2][8][4];
#pragma unroll
    for (int mt = 0; mt < 2; mt++)
#pragma unroll
        for (int nt = 0; nt < 8; nt++)
#pragma unroll
            for (int i = 0; i < 4; i++) acc[mt][nt][i] = 0.0f;

    auto prefetch = [&](int c, int b) {
#pragma unroll
        for (int t = 0; t < 4; t++) {
            int j   = t * 256 + tid;
            int row = j >> 3;
            int kq  = (j & 7) << 2;
            int grow = rowBase + row;
            cp16(smem + OFF_A(b) + row * LDPAD + kq,
                 x + (size_t)grow * D_IN + c * 32 + kq,
                 grow < N_NODES ? 16 : 0);
        }
#pragma unroll
        for (int t = 0; t < 4; t++) {
            int j   = t * 256 + tid;
            int row = j >> 3;
            int kq  = (j & 7) << 2;
            cp16(smem + OFF_B(b) + row * LDPAD + kq,
                 w + (size_t)row * D_IN + c * 32 + kq, 16);
        }
        CP_COMMIT();
    };

    prefetch(0, 0);
#pragma unroll
    for (int c = 0; c < 8; c++) {
        int buf = c & 1;
        if (c + 1 < 8) { prefetch(c + 1, buf ^ 1); CP_WAIT(1); }
        else           { CP_WAIT(0); }
        __syncthreads();

        const float* A = smem + OFF_A(buf);
        const float* B = smem + OFF_B(buf);
#pragma unroll
        for (int ks = 0; ks < 4; ks++) {
            int koff = ks * 8;
            float ah[2][4], alo[2][4];
#pragma unroll
            for (int mt = 0; mt < 2; mt++) {
                int r = wm * 32 + mt * 16 + ty;
                float a0 = A[(r    ) * LDPAD + koff + tx];
                float a1 = A[(r + 8) * LDPAD + koff + tx];
                float a2 = A[(r    ) * LDPAD + koff + tx + 4];
                float a3 = A[(r + 8) * LDPAD + koff + tx + 4];
                ah[mt][0] = trunc_tf32(a0); alo[mt][0] = a0 - ah[mt][0];
                ah[mt][1] = trunc_tf32(a1); alo[mt][1] = a1 - ah[mt][1];
                ah[mt][2] = trunc_tf32(a2); alo[mt][2] = a2 - ah[mt][2];
                ah[mt][3] = trunc_tf32(a3); alo[mt][3] = a3 - ah[mt][3];
            }
#pragma unroll
            for (int nt = 0; nt < 8; nt++) {
                int n = wn * 64 + nt * 8 + ty;
                float b0 = B[n * LDPAD + koff + tx];
                float b1 = B[n * LDPAD + koff + tx + 4];
                float bh0 = trunc_tf32(b0), bl0 = b0 - bh0;
                float bh1 = trunc_tf32(b1), bl1 = b1 - bh1;
#pragma unroll
                for (int mt = 0; mt < 2; mt++) {
                    mma_tf32_m16n8k8(acc[mt][nt], ah[mt],  bh0, bh1);
                    mma_tf32_m16n8k8(acc[mt][nt], ah[mt],  bl0, bl1);
                    mma_tf32_m16n8k8(acc[mt][nt], alo[mt], bh0, bh1);
                }
            }
        }
        __syncthreads();
    }

    // epilogue: store ft (fp16 pairs) + fused el/er (fp32, quad reduce)
#pragma unroll
    for (int mt = 0; mt < 2; mt++) {
#pragma unroll
        for (int half = 0; half < 2; half++) {
            int row = rowBase + wm * 32 + mt * 16 + ty + half * 8;
            bool valid = row < N_NODES;
            float el0 = 0.f, el1 = 0.f, er0 = 0.f, er1 = 0.f;
#pragma unroll
            for (int nt = 0; nt < 8; nt++) {
                int col = wn * 64 + nt * 8 + tx * 2;
                float d0 = acc[mt][nt][half * 2 + 0];
                float d1 = acc[mt][nt][half * 2 + 1];
                if (valid) {
                    __half2 hp = __floats2half2_rn(d0, d1);
                    g_fth[(size_t)row * 64 + (col >> 1)] = *(uint32_t*)&hp;
                }
                float l0 = al_s[col], l1 = al_s[col + 1];
                float r0 = ar_s[col], r1 = ar_s[col + 1];
                if (nt < 4) { el0 += d0 * l0 + d1 * l1; er0 += d0 * r0 + d1 * r1; }
                else        { el1 += d0 * l0 + d1 * l1; er1 += d0 * r0 + d1 * r1; }
            }
#pragma unroll
            for (int off = 1; off <= 2; off <<= 1) {
                el0 += __shfl_xor_sync(0xffffffffu, el0, off);
                el1 += __shfl_xor_sync(0xffffffffu, el1, off);
                er0 += __shfl_xor_sync(0xffffffffu, er0, off);
                er1 += __shfl_xor_sync(0xffffffffu, er1, off);
            }
            if (tx == 0 && valid) {
                int h0 = 2 * wn;
                g_el[row * N_HEADS + h0]     = el0;
                g_el[row * N_HEADS + h0 + 1] = el1;
                g_er[row * N_HEADS + h0]     = er0;
                g_er[row * N_HEADS + h0 + 1] = er1;
            }
        }
    }
}

__device__ __forceinline__ float lrelu(float v) { return v > 0.0f ? v : NEG_SLOPE * v; }

__device__ __forceinline__ void h2acc(uint2 v, float ex, float4& acc) {
    float2 p0 = __half22float2(*(__half2*)&v.x);
    float2 p1 = __half22float2(*(__half2*)&v.y);
    acc.x += ex * p0.x; acc.y += ex * p0.y;
    acc.z += ex * p1.x; acc.w += ex * p1.y;
}

// ---------------- K: aggregation (warp/node, fp16 ft gather, inline exp) ---------------
__global__ __launch_bounds__(256) void k_agg2(float* __restrict__ out) {
    int gw   = (blockIdx.x * blockDim.x + threadIdx.x) >> 5;
    int lane = threadIdx.x & 31;
    if (gw >= N_NODES) return;
    int cnt   = g_cnt[gw];
    int start = g_off[gw];
    int hsel  = lane >> 3;

    float er_u = g_er[gw * N_HEADS + hsel];

    float4 acc = make_float4(0.f, 0.f, 0.f, 0.f);
    float  dn  = 0.f;

    const int* srcA = g_srcv + start;

    int i = 0;
    for (; i + 4 <= cnt; i += 4) {
        int s0 = srcA[i], s1 = srcA[i + 1], s2 = srcA[i + 2], s3 = srcA[i + 3];
        float ex0 = expf(lrelu(g_el[s0 * N_HEADS + hsel] + er_u));
        float ex1 = expf(lrelu(g_el[s1 * N_HEADS + hsel] + er_u));
        float ex2 = expf(lrelu(g_el[s2 * N_HEADS + hsel] + er_u));
        float ex3 = expf(lrelu(g_el[s3 * N_HEADS + hsel] + er_u));
        uint2 f0 = ((const uint2*)(g_fth + (size_t)s0 * 64))[lane];
        uint2 f1 = ((const uint2*)(g_fth + (size_t)s1 * 64))[lane];
        uint2 f2 = ((const uint2*)(g_fth + (size_t)s2 * 64))[lane];
        uint2 f3 = ((const uint2*)(g_fth + (size_t)s3 * 64))[lane];
        h2acc(f0, ex0, acc);
        h2acc(f1, ex1, acc);
        h2acc(f2, ex2, acc);
        h2acc(f3, ex3, acc);
        dn += ex0 + ex1 + ex2 + ex3;
    }
    for (; i < cnt; i++) {
        int s = srcA[i];
        float ex = expf(lrelu(g_el[s * N_HEADS + hsel] + er_u));
        uint2 f = ((const uint2*)(g_fth + (size_t)s * 64))[lane];
        h2acc(f, ex, acc);
        dn += ex;
    }

    float4 o;
    if (cnt) {
        o.x = acc.x / dn; o.y = acc.y / dn;
        o.z = acc.z / dn; o.w = acc.w / dn;
    } else {
        o = make_float4(0.f, 0.f, 0.f, 0.f);
    }
    *(float4*)(out + (size_t)gw * D_HID + lane * 4) = o;
}

// ---------------- launch -----------------------------------------------------------------
extern "C" void kernel_launch(void* const* d_in, const int* in_sizes, int n_in,
                              void* d_out, int out_size) {
    const float* x   = (const float*)d_in[0];
    const float* w   = (const float*)d_in[1];
    const float* al  = (const float*)d_in[2];
    const float* ar  = (const float*)d_in[3];
    const int*   src = (const int*)d_in[4];
    const int*   dst = (const int*)d_in[5];
    float*       out = (float*)d_out;

    static bool init_done = false;
    static cudaStream_t s2;
    static cudaEvent_t evFork, evJoin;
    static void* cntAddr = nullptr;
    if (!init_done) {
        cudaFuncSetAttribute(k_gemm_mma, cudaFuncAttributeMaxDynamicSharedMemorySize, SMEM_BYTES);
        cudaStreamCreateWithFlags(&s2, cudaStreamNonBlocking);
        cudaEventCreateWithFlags(&evFork, cudaEventDisableTiming);
        cudaEventCreateWithFlags(&evJoin, cudaEventDisableTiming);
        cudaGetSymbolAddress(&cntAddr, g_cnt);
        init_done = true;
    }

    // fork: edge-indexing chain on s2, independent of the GEMM
    cudaEventRecord(evFork, 0);
    cudaStreamWaitEvent(s2, evFork, 0);
    cudaMemsetAsync(cntAddr, 0, N_NODES * sizeof(int), s2);
    k_hist<<<(N_EDGES + 255) / 256, 256, 0, s2>>>(dst);
    k_scan1<<<NB, SCAN_B, 0, s2>>>();
    k_scan2<<<1, 256, 0, s2>>>();
    k_scan3<<<NB, SCAN_B, 0, s2>>>();
    k_scatter<<<(N_EDGES + 255) / 256, 256, 0, s2>>>(src, dst);
    cudaEventRecord(evJoin, s2);

    k_gemm_mma<<<(N_NODES + 127) / 128, 256, SMEM_BYTES>>>(x, w, al, ar);

    // join: agg2 needs srcv/cnt/off (s2) + fth/el/er (GEMM)
    cudaStreamWaitEvent(0, evJoin, 0);
    k_agg2<<<(N_NODES * 32 + 255) / 256, 256>>>(out);
}

// round 12
// speedup vs baseline: 1.2957x; 1.0654x over previous
#include <cuda_runtime.h>
#include <cuda_fp16.h>
#include <cstdint>

#define N_NODES 100000
#define N_EDGES 1600000
#define D_IN    256
#define N_HEADS 4
#define D_OUT   32
#define D_HID   128
#define NEG_SLOPE 0.2f

#define SCAN_B 512
#define NB ((N_NODES + SCAN_B - 1) / SCAN_B)   // 196

// ---------------- scratch (static device globals) ----------------------------
__device__ uint32_t g_fth[N_NODES * 64];     // ft as half2 pairs: 25.6 MB
__device__ float  g_el[N_NODES * N_HEADS];
__device__ float  g_er[N_NODES * N_HEADS];
__device__ int    g_cnt[N_NODES];
__device__ int    g_scan[N_NODES];
__device__ int    g_off[N_NODES];
__device__ int    g_cursor[N_NODES];
__device__ int    g_btot[256];
__device__ int    g_boff[256];
__device__ int    g_srcv[N_EDGES];

// ---------------- K: histogram of dst ------------------------------------------
__global__ void k_hist(const int* __restrict__ dst) {
    int e = blockIdx.x * blockDim.x + threadIdx.x;
    if (e >= N_EDGES) return;
    int d = dst[e];
    if ((unsigned)d < N_NODES) atomicAdd(&g_cnt[d], 1);
}

// ---------------- K: scan stages ---------------------------------------------------
__global__ __launch_bounds__(SCAN_B) void k_scan1() {
    __shared__ int sh[SCAN_B];
    int i = blockIdx.x * SCAN_B + threadIdx.x;
    int v = (i < N_NODES) ? g_cnt[i] : 0;
    sh[threadIdx.x] = v;
    __syncthreads();
#pragma unroll
    for (int off = 1; off < SCAN_B; off <<= 1) {
        int t = (threadIdx.x >= off) ? sh[threadIdx.x - off] : 0;
        __syncthreads();
        sh[threadIdx.x] += t;
        __syncthreads();
    }
    if (i < N_NODES) g_scan[i] = sh[threadIdx.x];
    if (threadIdx.x == SCAN_B - 1) g_btot[blockIdx.x] = sh[SCAN_B - 1];
}

__global__ __launch_bounds__(256) void k_scan2() {
    __shared__ int sh[256];
    int tid = threadIdx.x;
    int v = (tid < NB) ? g_btot[tid] : 0;
    sh[tid] = v;
    __syncthreads();
#pragma unroll
    for (int off = 1; off < 256; off <<= 1) {
        int t = (tid >= off) ? sh[tid - off] : 0;
        __syncthreads();
        sh[tid] += t;
        __syncthreads();
    }
    if (tid < NB) g_boff[tid] = sh[tid] - v;
}

__global__ __launch_bounds__(SCAN_B) void k_scan3() {
    int i = blockIdx.x * SCAN_B + threadIdx.x;
    if (i < N_NODES) {
        int off = g_scan[i] - g_cnt[i] + g_boff[blockIdx.x];
        g_off[i]    = off;
        g_cursor[i] = off;
    }
}

// ---------------- K: scatter (src-only) ----------------------------------------------
__global__ void k_scatter(const int* __restrict__ src, const int* __restrict__ dst) {
    int e = blockIdx.x * blockDim.x + threadIdx.x;
    if (e >= N_EDGES) return;
    int s = src[e], d = dst[e];
    if ((unsigned)s >= N_NODES || (unsigned)d >= N_NODES) return;
    int pos = atomicAdd(&g_cursor[d], 1);
    g_srcv[pos] = s;
}

// ---------------- helpers -------------------------------------------------------------
__device__ __forceinline__ float trunc_tf32(float f) {
    return __uint_as_float(__float_as_uint(f) & 0xFFFFE000u);
}
__device__ __forceinline__ uint32_t smem_u32(const void* p) {
    uint32_t a;
    asm("{ .reg .u64 t; cvta.to.shared.u64 t, %1; cvt.u32.u64 %0, t; }" : "=r"(a) : "l"(p));
    return a;
}
__device__ __forceinline__ void cp16(void* sdst, const void* gsrc, int srcbytes) {
    asm volatile("cp.async.cg.shared.global [%0], [%1], 16, %2;"
                 :: "r"(smem_u32(sdst)), "l"(gsrc), "r"(srcbytes));
}
#define CP_COMMIT() asm volatile("cp.async.commit_group;" ::: "memory")
#define CP_WAIT(n)  asm volatile("cp.async.wait_group %0;" :: "n"(n) : "memory")

__device__ __forceinline__ void mma_tf32_m16n8k8(float* d, const float* a, float b0, float b1) {
    asm volatile(
        "mma.sync.aligned.m16n8k8.row.col.f32.tf32.tf32.f32 "
        "{%0,%1,%2,%3}, {%4,%5,%6,%7}, {%8,%9}, {%0,%1,%2,%3};"
        : "+f"(d[0]), "+f"(d[1]), "+f"(d[2]), "+f"(d[3])
        : "r"(__float_as_uint(a[0])), "r"(__float_as_uint(a[1])),
          "r"(__float_as_uint(a[2])), "r"(__float_as_uint(a[3])),
          "r"(__float_as_uint(b0)),  "r"(__float_as_uint(b1)));
}

// SMEM layout: A double buffer + B double buffer + al/ar
#define LDPAD 36
#define TILE_FLOATS (128 * LDPAD)
#define OFF_A(b) ((b) * TILE_FLOATS)
#define OFF_B(b) ((2 + (b)) * TILE_FLOATS)
#define OFF_ALS  (4 * TILE_FLOATS)
#define OFF_ARS  (4 * TILE_FLOATS + 128)
#define SMEM_FLOATS (4 * TILE_FLOATS + 256)
#define SMEM_BYTES (SMEM_FLOATS * 4)

// ---------------- K: cp.async double-buffered 3xTF32 GEMM + fused el/er -----------
__global__ __launch_bounds__(256) void k_gemm_mma(const float* __restrict__ x,
                                                  const float* __restrict__ w,
                                                  const float* __restrict__ al,
                                                  const float* __restrict__ ar) {
    extern __shared__ __align__(16) float smem[];
    float* al_s = smem + OFF_ALS;
    float* ar_s = smem + OFF_ARS;

    const int tid  = threadIdx.x;
    const int lane = tid & 31;
    const int warp = tid >> 5;
    const int wm   = warp >> 1;
    const int wn   = warp & 1;
    const int ty   = lane >> 2;
    const int tx   = lane & 3;
    const int rowBase = blockIdx.x * 128;

    if (tid < 128) { al_s[tid] = al[tid]; ar_s[tid] = ar[tid]; }

    float acc[2][8][4];
#pragma unroll
    for (int mt = 0; mt < 2; mt++)
#pragma unroll
        for (int nt = 0; nt < 8; nt++)
#pragma unroll
            for (int i = 0; i < 4; i++) acc[mt][nt][i] = 0.0f;

    auto prefetch = [&](int c, int b) {
#pragma unroll
        for (int t = 0; t < 4; t++) {
            int j   = t * 256 + tid;
            int row = j >> 3;
            int kq  = (j & 7) << 2;
            int grow = rowBase + row;
            cp16(smem + OFF_A(b) + row * LDPAD + kq,
                 x + (size_t)grow * D_IN + c * 32 + kq,
                 grow < N_NODES ? 16 : 0);
        }
#pragma unroll
        for (int t = 0; t < 4; t++) {
            int j   = t * 256 + tid;
            int row = j >> 3;
            int kq  = (j & 7) << 2;
            cp16(smem + OFF_B(b) + row * LDPAD + kq,
                 w + (size_t)row * D_IN + c * 32 + kq, 16);
        }
        CP_COMMIT();
    };

    prefetch(0, 0);
#pragma unroll
    for (int c = 0; c < 8; c++) {
        int buf = c & 1;
        if (c + 1 < 8) { prefetch(c + 1, buf ^ 1); CP_WAIT(1); }
        else           { CP_WAIT(0); }
        __syncthreads();

        const float* A = smem + OFF_A(buf);
        const float* B = smem + OFF_B(buf);
#pragma unroll
        for (int ks = 0; ks < 4; ks++) {
            int koff = ks * 8;
            float ah[2][4], alo[2][4];
#pragma unroll
            for (int mt = 0; mt < 2; mt++) {
                int r = wm * 32 + mt * 16 + ty;
                float a0 = A[(r    ) * LDPAD + koff + tx];
                float a1 = A[(r + 8) * LDPAD + koff + tx];
                float a2 = A[(r    ) * LDPAD + koff + tx + 4];
                float a3 = A[(r + 8) * LDPAD + koff + tx + 4];
                ah[mt][0] = trunc_tf32(a0); alo[mt][0] = a0 - ah[mt][0];
                ah[mt][1] = trunc_tf32(a1); alo[mt][1] = a1 - ah[mt][1];
                ah[mt][2] = trunc_tf32(a2); alo[mt][2] = a2 - ah[mt][2];
                ah[mt][3] = trunc_tf32(a3); alo[mt][3] = a3 - ah[mt][3];
            }
#pragma unroll
            for (int nt = 0; nt < 8; nt++) {
                int n = wn * 64 + nt * 8 + ty;
                float b0 = B[n * LDPAD + koff + tx];
                float b1 = B[n * LDPAD + koff + tx + 4];
                float bh0 = trunc_tf32(b0), bl0 = b0 - bh0;
                float bh1 = trunc_tf32(b1), bl1 = b1 - bh1;
#pragma unroll
                for (int mt = 0; mt < 2; mt++) {
                    mma_tf32_m16n8k8(acc[mt][nt], ah[mt],  bh0, bh1);
                    mma_tf32_m16n8k8(acc[mt][nt], ah[mt],  bl0, bl1);
                    mma_tf32_m16n8k8(acc[mt][nt], alo[mt], bh0, bh1);
                }
            }
        }
        __syncthreads();
    }

    // epilogue: store ft (fp16 pairs) + fused el/er (fp32, quad reduce)
#pragma unroll
    for (int mt = 0; mt < 2; mt++) {
#pragma unroll
        for (int half = 0; half < 2; half++) {
            int row = rowBase + wm * 32 + mt * 16 + ty + half * 8;
            bool valid = row < N_NODES;
            float el0 = 0.f, el1 = 0.f, er0 = 0.f, er1 = 0.f;
#pragma unroll
            for (int nt = 0; nt < 8; nt++) {
                int col = wn * 64 + nt * 8 + tx * 2;
                float d0 = acc[mt][nt][half * 2 + 0];
                float d1 = acc[mt][nt][half * 2 + 1];
                if (valid) {
                    __half2 hp = __floats2half2_rn(d0, d1);
                    g_fth[(size_t)row * 64 + (col >> 1)] = *(uint32_t*)&hp;
                }
                float l0 = al_s[col], l1 = al_s[col + 1];
                float r0 = ar_s[col], r1 = ar_s[col + 1];
                if (nt < 4) { el0 += d0 * l0 + d1 * l1; er0 += d0 * r0 + d1 * r1; }
                else        { el1 += d0 * l0 + d1 * l1; er1 += d0 * r0 + d1 * r1; }
            }
#pragma unroll
            for (int off = 1; off <= 2; off <<= 1) {
                el0 += __shfl_xor_sync(0xffffffffu, el0, off);
                el1 += __shfl_xor_sync(0xffffffffu, el1, off);
                er0 += __shfl_xor_sync(0xffffffffu, er0, off);
                er1 += __shfl_xor_sync(0xffffffffu, er1, off);
            }
            if (tx == 0 && valid) {
                int h0 = 2 * wn;
                g_el[row * N_HEADS + h0]     = el0;
                g_el[row * N_HEADS + h0 + 1] = el1;
                g_er[row * N_HEADS + h0]     = er0;
                g_er[row * N_HEADS + h0 + 1] = er1;
            }
        }
    }
}

// fast edge weight: __expf of leaky-relu
__device__ __forceinline__ float edge_ex(float v) {
    float lr = fmaxf(v, 0.f) + NEG_SLOPE * fminf(v, 0.f);
    return __expf(lr);
}

__device__ __forceinline__ void h2acc(uint2 v, float ex, float4& acc) {
    float2 p0 = __half22float2(*(__half2*)&v.x);
    float2 p1 = __half22float2(*(__half2*)&v.y);
    acc.x += ex * p0.x; acc.y += ex * p0.y;
    acc.z += ex * p1.x; acc.w += ex * p1.y;
}

// ---------------- K: aggregation (warp/node, fp16 ft, int4 src, __expf) ---------------
__global__ __launch_bounds__(256) void k_agg2(float* __restrict__ out) {
    int gw   = (blockIdx.x * blockDim.x + threadIdx.x) >> 5;
    int lane = threadIdx.x & 31;
    if (gw >= N_NODES) return;
    int cnt   = g_cnt[gw];
    int start = g_off[gw];
    int hsel  = lane >> 3;

    float er_u = g_er[gw * N_HEADS + hsel];

    float4 acc = make_float4(0.f, 0.f, 0.f, 0.f);
    float  dn  = 0.f;

    const int* srcA = g_srcv + start;

    int i = 0;
    // peel to 16B alignment of srcA
    int pre = (4 - (start & 3)) & 3;
    if (pre > cnt) pre = cnt;
    for (; i < pre; i++) {
        int s = srcA[i];
        float ex = edge_ex(g_el[s * N_HEADS + hsel] + er_u);
        uint2 f = ((const uint2*)(g_fth + (size_t)s * 64))[lane];
        h2acc(f, ex, acc);
        dn += ex;
    }
    for (; i + 4 <= cnt; i += 4) {
        int4 s4 = *(const int4*)(srcA + i);
        float ex0 = edge_ex(g_el[s4.x * N_HEADS + hsel] + er_u);
        float ex1 = edge_ex(g_el[s4.y * N_HEADS + hsel] + er_u);
        float ex2 = edge_ex(g_el[s4.z * N_HEADS + hsel] + er_u);
        float ex3 = edge_ex(g_el[s4.w * N_HEADS + hsel] + er_u);
        uint2 f0 = ((const uint2*)(g_fth + (size_t)s4.x * 64))[lane];
        uint2 f1 = ((const uint2*)(g_fth + (size_t)s4.y * 64))[lane];
        uint2 f2 = ((const uint2*)(g_fth + (size_t)s4.z * 64))[lane];
        uint2 f3 = ((const uint2*)(g_fth + (size_t)s4.w * 64))[lane];
        h2acc(f0, ex0, acc);
        h2acc(f1, ex1, acc);
        h2acc(f2, ex2, acc);
        h2acc(f3, ex3, acc);
        dn += ex0 + ex1 + ex2 + ex3;
    }
    for (; i < cnt; i++) {
        int s = srcA[i];
        float ex = edge_ex(g_el[s * N_HEADS + hsel] + er_u);
        uint2 f = ((const uint2*)(g_fth + (size_t)s * 64))[lane];
        h2acc(f, ex, acc);
        dn += ex;
    }

    float4 o;
    if (cnt) {
        float r = __fdividef(1.f, dn);
        o.x = acc.x * r; o.y = acc.y * r;
        o.z = acc.z * r; o.w = acc.w * r;
    } else {
        o = make_float4(0.f, 0.f, 0.f, 0.f);
    }
    *(float4*)(out + (size_t)gw * D_HID + lane * 4) = o;
}

// ---------------- launch -----------------------------------------------------------------
extern "C" void kernel_launch(void* const* d_in, const int* in_sizes, int n_in,
                              void* d_out, int out_size) {
    const float* x   = (const float*)d_in[0];
    const float* w   = (const float*)d_in[1];
    const float* al  = (const float*)d_in[2];
    const float* ar  = (const float*)d_in[3];
    const int*   src = (const int*)d_in[4];
    const int*   dst = (const int*)d_in[5];
    float*       out = (float*)d_out;

    static bool init_done = false;
    static cudaStream_t s2;
    static cudaEvent_t evFork, evJoin;
    static void* cntAddr = nullptr;
    if (!init_done) {
        cudaFuncSetAttribute(k_gemm_mma, cudaFuncAttributeMaxDynamicSharedMemorySize, SMEM_BYTES);
        cudaStreamCreateWithFlags(&s2, cudaStreamNonBlocking);
        cudaEventCreateWithFlags(&evFork, cudaEventDisableTiming);
        cudaEventCreateWithFlags(&evJoin, cudaEventDisableTiming);
        cudaGetSymbolAddress(&cntAddr, g_cnt);
        init_done = true;
    }

    // fork: edge-indexing chain on s2, independent of the GEMM
    cudaEventRecord(evFork, 0);
    cudaStreamWaitEvent(s2, evFork, 0);
    cudaMemsetAsync(cntAddr, 0, N_NODES * sizeof(int), s2);
    k_hist<<<(N_EDGES + 255) / 256, 256, 0, s2>>>(dst);
    k_scan1<<<NB, SCAN_B, 0, s2>>>();
    k_scan2<<<1, 256, 0, s2>>>();
    k_scan3<<<NB, SCAN_B, 0, s2>>>();
    k_scatter<<<(N_EDGES + 255) / 256, 256, 0, s2>>>(src, dst);
    cudaEventRecord(evJoin, s2);

    k_gemm_mma<<<(N_NODES + 127) / 128, 256, SMEM_BYTES>>>(x, w, al, ar);

    // join: agg2 needs srcv/cnt/off (s2) + fth/el/er (GEMM)
    cudaStreamWaitEvent(0, evJoin, 0);
    k_agg2<<<(N_NODES * 32 + 255) / 256, 256>>>(out);
}